// round 1
// baseline (speedup 1.0000x reference)
#include <cuda_runtime.h>

typedef unsigned long long u64;
typedef unsigned int u32;

#define NB 16
#define NPT 4096
#define NS 1024
#define NK 32

// ---------------- device scratch (static, no runtime allocation) ----------------
__device__ __align__(16) float g_P0[NB * NPT * 64];   // points @ scaled W0_pts + beta0  (16.7 MB)
__device__ __align__(16) float g_W0x[3 * 64];         // scaled xyz part of W0, [i][o]
__device__ __align__(16) float g_W0p[64 * 64];        // scaled points part of W0, [c][o]
__device__ __align__(16) float g_B0[64];
__device__ __align__(16) float g_W1[64 * 64];         // [i][o], BN-scaled
__device__ __align__(16) float g_B1[64];
__device__ __align__(16) float g_W2[64 * 128];        // [i][o], BN-scaled
__device__ __align__(16) float g_B2[128];
__device__ int g_knn[NB * NS * NK];

// ---------------- packed f32x2 helpers (Blackwell FFMA2) ----------------
__device__ __forceinline__ u64 ffma2(u64 a, u64 b, u64 c) {
    u64 d;
    asm("fma.rn.f32x2 %0, %1, %2, %3;" : "=l"(d) : "l"(a), "l"(b), "l"(c));
    return d;
}
__device__ __forceinline__ u64 dup2(float x) {
    u64 r;
    asm("mov.b64 %0, {%1, %1};" : "=l"(r) : "f"(x));
    return r;
}
__device__ __forceinline__ void unpack2(u64 a, float& lo, float& hi) {
    asm("mov.b64 {%0, %1}, %2;" : "=f"(lo), "=f"(hi) : "l"(a));
}
__device__ __forceinline__ float warp_max32(float v) {
#pragma unroll
    for (int off = 16; off > 0; off >>= 1)
        v = fmaxf(v, __shfl_xor_sync(0xffffffffu, v, off));
    return v;
}

// ---------------- kernel 1: fold BN into weights ----------------
__global__ void prep_kernel(
    const float* w0, const float* cb0, const float* g0, const float* b0, const float* m0, const float* v0,
    const float* w1, const float* cb1, const float* g1, const float* b1, const float* m1, const float* v1,
    const float* w2, const float* cb2, const float* g2, const float* b2, const float* m2, const float* v2)
{
    int o = threadIdx.x;
    if (o < 64) {
        float s0 = g0[o] / sqrtf(v0[o] + 1e-5f);
        g_B0[o] = (cb0[o] - m0[o]) * s0 + b0[o];
        for (int i = 0; i < 3; i++)  g_W0x[i * 64 + o] = w0[o * 67 + i] * s0;
        for (int c = 0; c < 64; c++) g_W0p[c * 64 + o] = w0[o * 67 + 3 + c] * s0;

        float s1 = g1[o] / sqrtf(v1[o] + 1e-5f);
        g_B1[o] = (cb1[o] - m1[o]) * s1 + b1[o];
        for (int i = 0; i < 64; i++) g_W1[i * 64 + o] = w1[o * 64 + i] * s1;
    }
    if (o < 128) {
        float s2 = g2[o] / sqrtf(v2[o] + 1e-5f);
        g_B2[o] = (cb2[o] - m2[o]) * s2 + b2[o];
        for (int i = 0; i < 64; i++) g_W2[i * 128 + o] = w2[o * 64 + i] * s2;
    }
}

// ---------------- kernel 2: FPS (blocks 0..15) + P0 precompute (blocks 16..271) ----------------
__global__ __launch_bounds__(256) void fps_p0_kernel(
    const float* __restrict__ xyz, const float* __restrict__ points, float* __restrict__ out_newxyz)
{
    __shared__ float sc[3];
    __shared__ u64 sKey[8];
    __shared__ __align__(16) float sW[64 * 64 + 64];

    if (blockIdx.x < NB) {
        // ---- farthest point sampling, one block per batch ----
        int b = blockIdx.x;
        int t = threadIdx.x;
        const float* xb = xyz + (size_t)b * NPT * 3;

        float px[16], py[16], pz[16], dd[16];
#pragma unroll
        for (int j = 0; j < 16; j++) {
            int n = t + 256 * j;
            px[j] = xb[n * 3 + 0];
            py[j] = xb[n * 3 + 1];
            pz[j] = xb[n * 3 + 2];
            dd[j] = 1e10f;
        }

        // emit centroid 0 (deterministic start at index 0)
        if (t == 0) {
            sc[0] = px[0]; sc[1] = py[0]; sc[2] = pz[0];
            float* o0 = out_newxyz + (size_t)b * NS * 3;
            o0[0] = px[0]; o0[1] = py[0]; o0[2] = pz[0];
        }
        __syncthreads();

        int lane = t & 31, w = t >> 5;
        for (int it = 0; it < NS - 1; it++) {
            float cx = sc[0], cy = sc[1], cz = sc[2];
            // update running min-distance, build local argmax key
            u64 best = 0;
#pragma unroll
            for (int j = 0; j < 16; j++) {
                float dx = px[j] - cx, dy = py[j] - cy, dz = pz[j] - cz;
                // exact reference order, no FMA contraction: (dx^2 + dy^2) + dz^2
                float d2 = __fadd_rn(__fadd_rn(__fmul_rn(dx, dx), __fmul_rn(dy, dy)), __fmul_rn(dz, dz));
                float nd = fminf(dd[j], d2);
                dd[j] = nd;
                int n = t + 256 * j;
                u64 key = ((u64)__float_as_uint(nd) << 32) | (u32)(~(u32)n); // max dist, tie -> min index
                best = (key > best) ? key : best;
            }
            // warp argmax via redux.sync
            u32 hi = (u32)(best >> 32);
            u32 H = __reduce_max_sync(0xffffffffu, hi);
            u32 cand = (hi == H) ? (u32)best : 0u;
            u32 L = __reduce_max_sync(0xffffffffu, cand);
            if (lane == 0) sKey[w] = ((u64)H << 32) | (u64)L;
            __syncthreads();
            // every thread scans 8 warp keys
            u64 g = sKey[0];
#pragma unroll
            for (int q = 1; q < 8; q++) { u64 k2 = sKey[q]; g = (k2 > g) ? k2 : g; }
            int n = (int)(~((u32)g)) & (NPT - 1);
            if (t == (n & 255)) {
                int jj = n >> 8;
                float wx = 0.f, wy = 0.f, wz = 0.f;
#pragma unroll
                for (int j = 0; j < 16; j++)
                    if (jj == j) { wx = px[j]; wy = py[j]; wz = pz[j]; }
                sc[0] = wx; sc[1] = wy; sc[2] = wz;
                float* oo = out_newxyz + ((size_t)b * NS + (it + 1)) * 3;
                oo[0] = wx; oo[1] = wy; oo[2] = wz;
            }
            __syncthreads();
        }
    } else {
        // ---- P0: points @ (W0_pts * s0) + beta0, one thread per (b,n) ----
        int pid = (blockIdx.x - NB) * 256 + threadIdx.x;  // 0..65535
        for (int i = threadIdx.x; i < 64 * 64; i += 256) sW[i] = g_W0p[i];
        for (int i = threadIdx.x; i < 64; i += 256) sW[64 * 64 + i] = g_B0[i];
        __syncthreads();

        float xr[64];
        const float4* pr = (const float4*)(points + (size_t)pid * 64);
#pragma unroll
        for (int q = 0; q < 16; q++) {
            float4 v = __ldg(pr + q);
            xr[4 * q + 0] = v.x; xr[4 * q + 1] = v.y; xr[4 * q + 2] = v.z; xr[4 * q + 3] = v.w;
        }
        u64 acc[32];
        const u64* bb = (const u64*)(sW + 64 * 64);
#pragma unroll
        for (int q = 0; q < 32; q++) acc[q] = bb[q];
#pragma unroll
        for (int c = 0; c < 64; c++) {
            u64 xi = dup2(xr[c]);
            const ulonglong2* wr = (const ulonglong2*)(sW + c * 64);
#pragma unroll
            for (int q = 0; q < 16; q++) {
                ulonglong2 wv = wr[q];
                acc[2 * q]     = ffma2(xi, wv.x, acc[2 * q]);
                acc[2 * q + 1] = ffma2(xi, wv.y, acc[2 * q + 1]);
            }
        }
        ulonglong2* op = (ulonglong2*)(g_P0 + (size_t)pid * 64);
#pragma unroll
        for (int q = 0; q < 16; q++) op[q] = make_ulonglong2(acc[2 * q], acc[2 * q + 1]);
    }
}

// ---------------- kernel 3: KNN (32 smallest of 4096 per centroid) ----------------
__global__ __launch_bounds__(128) void knn_kernel(
    const float* __restrict__ xyz, const float* __restrict__ newxyz)
{
    int s = blockIdx.x, b = blockIdx.y;
    int t = threadIdx.x, lane = t & 31, w = t >> 5;
    const float* c3 = newxyz + ((size_t)b * NS + s) * 3;
    float cx = c3[0], cy = c3[1], cz = c3[2];
    const float* xb = xyz + (size_t)b * NPT * 3;

    float d[32];
#pragma unroll
    for (int j = 0; j < 32; j++) {
        int n = t + 128 * j;
        float dx = __ldg(xb + n * 3 + 0) - cx;
        float dy = __ldg(xb + n * 3 + 1) - cy;
        float dz = __ldg(xb + n * 3 + 2) - cz;
        d[j] = __fadd_rn(__fadd_rn(__fmul_rn(dx, dx), __fmul_rn(dy, dy)), __fmul_rn(dz, dz));
    }
    // cached local min key: (dist bits << 32) | n  -> min key = min dist, tie min n
    u64 lk = ~0ull;
#pragma unroll
    for (int j = 0; j < 32; j++) {
        u64 key = ((u64)__float_as_uint(d[j]) << 32) | (u32)(t + 128 * j);
        lk = (key < lk) ? key : lk;
    }
    __shared__ u64 sW4[4];
    __shared__ u64 sG;
    int* out = g_knn + ((size_t)b * NS + s) * NK;

    for (int r = 0; r < NK; r++) {
        u32 hi = (u32)(lk >> 32);
        u32 H = __reduce_min_sync(0xffffffffu, hi);
        u32 cand = (hi == H) ? (u32)lk : 0xffffffffu;
        u32 L = __reduce_min_sync(0xffffffffu, cand);
        if (lane == 0) sW4[w] = ((u64)H << 32) | (u64)L;
        __syncthreads();
        if (t == 0) {
            u64 g = sW4[0];
#pragma unroll
            for (int q = 1; q < 4; q++) { u64 k2 = sW4[q]; g = (k2 < g) ? k2 : g; }
            sG = g;
            out[r] = (int)((u32)g);
        }
        __syncthreads();
        u64 g = sG;
        if (lk == g) {  // unique winner (index embedded in key)
#pragma unroll
            for (int j = 0; j < 32; j++) {
                u64 key = ((u64)__float_as_uint(d[j]) << 32) | (u32)(t + 128 * j);
                if (key == g) d[j] = __uint_as_float(0x7f800000u);  // +inf
            }
            lk = ~0ull;
#pragma unroll
            for (int j = 0; j < 32; j++) {
                u64 key = ((u64)__float_as_uint(d[j]) << 32) | (u32)(t + 128 * j);
                lk = (key < lk) ? key : lk;
            }
        }
    }
}

// ---------------- kernel 4: fused MLP (layers 0..2) + max over K ----------------
// warp = one centroid, lane = one neighbor. f32x2 packed FMA throughout.
extern __shared__ __align__(16) float smem[];
__global__ __launch_bounds__(256, 1) void mlp_kernel(
    const float* __restrict__ xyz, float* __restrict__ out)  // out = full d_out base
{
    float* sW1 = smem;            // 4096 floats
    float* sW2 = smem + 4096;     // 8192 floats
    float* sB1 = smem + 12288;    // 64
    float* sB2 = smem + 12352;    // 128
    float* sW0x = smem + 12480;   // 192
    for (int i = threadIdx.x; i < 4096; i += 256) sW1[i] = g_W1[i];
    for (int i = threadIdx.x; i < 8192; i += 256) sW2[i] = g_W2[i];
    for (int i = threadIdx.x; i < 64; i += 256) sB1[i] = g_B1[i];
    for (int i = threadIdx.x; i < 128; i += 256) sB2[i] = g_B2[i];
    for (int i = threadIdx.x; i < 192; i += 256) sW0x[i] = g_W0x[i];
    __syncthreads();

    int w = threadIdx.x >> 5, k = threadIdx.x & 31;
    int sg = blockIdx.x * 8 + w;          // global centroid id (b*NS + s)
    int b = sg >> 10, s = sg & (NS - 1);
    int n = g_knn[(size_t)sg * NK + k];

    const float* c3 = out + (size_t)sg * 3;  // new_xyz region of d_out
    float cx = c3[0], cy = c3[1], cz = c3[2];
    const float* xp = xyz + ((size_t)b * NPT + n) * 3;
    float gx = xp[0] - cx, gy = xp[1] - cy, gz = xp[2] - cz;
    u64 dgx = dup2(gx), dgy = dup2(gy), dgz = dup2(gz);

    // ---- layer 0: relu( gxyz @ W0x + P0row )   (P0 already has points-part + beta0) ----
    float x0[64];
    const ulonglong2* pr = (const ulonglong2*)(g_P0 + ((size_t)b * NPT + n) * 64);
    const ulonglong2* w0r0 = (const ulonglong2*)(sW0x);
    const ulonglong2* w0r1 = (const ulonglong2*)(sW0x + 64);
    const ulonglong2* w0r2 = (const ulonglong2*)(sW0x + 128);
#pragma unroll
    for (int q = 0; q < 16; q++) {
        ulonglong2 p = __ldg(pr + q);
        u64 a0 = p.x, a1 = p.y;
        ulonglong2 w0v = w0r0[q]; a0 = ffma2(dgx, w0v.x, a0); a1 = ffma2(dgx, w0v.y, a1);
        ulonglong2 w1v = w0r1[q]; a0 = ffma2(dgy, w1v.x, a0); a1 = ffma2(dgy, w1v.y, a1);
        ulonglong2 w2v = w0r2[q]; a0 = ffma2(dgz, w2v.x, a0); a1 = ffma2(dgz, w2v.y, a1);
        float l0, h0, l1, h1;
        unpack2(a0, l0, h0); unpack2(a1, l1, h1);
        x0[4 * q + 0] = fmaxf(l0, 0.f); x0[4 * q + 1] = fmaxf(h0, 0.f);
        x0[4 * q + 2] = fmaxf(l1, 0.f); x0[4 * q + 3] = fmaxf(h1, 0.f);
    }

    // ---- layer 1: 64 -> 64 ----
    {
        u64 acc[32];
        const u64* bb = (const u64*)sB1;
#pragma unroll
        for (int q = 0; q < 32; q++) acc[q] = bb[q];
#pragma unroll
        for (int i = 0; i < 64; i++) {
            u64 xi = dup2(x0[i]);
            const ulonglong2* wr = (const ulonglong2*)(sW1 + i * 64);
#pragma unroll
            for (int q = 0; q < 16; q++) {
                ulonglong2 wv = wr[q];
                acc[2 * q]     = ffma2(xi, wv.x, acc[2 * q]);
                acc[2 * q + 1] = ffma2(xi, wv.y, acc[2 * q + 1]);
            }
        }
#pragma unroll
        for (int q = 0; q < 32; q++) {
            float lo, hi;
            unpack2(acc[q], lo, hi);
            x0[2 * q] = fmaxf(lo, 0.f); x0[2 * q + 1] = fmaxf(hi, 0.f);
        }
    }

    // ---- layer 2: 64 -> 128 in two halves, relu, warp-max over K, write [b][c][s] ----
    float* outbase = out + (size_t)NB * NS * 3 + ((size_t)b * 128) * NS + s;
    for (int h = 0; h < 2; h++) {
        u64 acc[32];
        const u64* bb = (const u64*)sB2;
#pragma unroll
        for (int q = 0; q < 32; q++) acc[q] = bb[h * 32 + q];
#pragma unroll
        for (int i = 0; i < 64; i++) {
            u64 xi = dup2(x0[i]);
            const ulonglong2* wr = (const ulonglong2*)(sW2 + i * 128 + h * 64);
#pragma unroll
            for (int q = 0; q < 16; q++) {
                ulonglong2 wv = wr[q];
                acc[2 * q]     = ffma2(xi, wv.x, acc[2 * q]);
                acc[2 * q + 1] = ffma2(xi, wv.y, acc[2 * q + 1]);
            }
        }
#pragma unroll
        for (int q = 0; q < 32; q++) {
            float lo, hi;
            unpack2(acc[q], lo, hi);
            lo = warp_max32(fmaxf(lo, 0.f));
            hi = warp_max32(fmaxf(hi, 0.f));
            if (k == q) {  // lane q writes channels 2q, 2q+1 of this half
                outbase[(size_t)(h * 64 + 2 * q) * NS] = lo;
                outbase[(size_t)(h * 64 + 2 * q + 1) * NS] = hi;
            }
        }
    }
}

// ---------------- launch ----------------
extern "C" void kernel_launch(void* const* d_in, const int* in_sizes, int n_in,
                              void* d_out, int out_size)
{
    const float* xyz = (const float*)d_in[0];
    const float* points = (const float*)d_in[1];
    const float* w0 = (const float*)d_in[2];
    const float* cb0 = (const float*)d_in[3];
    const float* g0 = (const float*)d_in[4];
    const float* b0 = (const float*)d_in[5];
    const float* m0 = (const float*)d_in[6];
    const float* v0 = (const float*)d_in[7];
    const float* w1 = (const float*)d_in[8];
    const float* cb1 = (const float*)d_in[9];
    const float* g1 = (const float*)d_in[10];
    const float* b1 = (const float*)d_in[11];
    const float* m1 = (const float*)d_in[12];
    const float* v1 = (const float*)d_in[13];
    const float* w2 = (const float*)d_in[14];
    const float* cb2 = (const float*)d_in[15];
    const float* g2 = (const float*)d_in[16];
    const float* b2 = (const float*)d_in[17];
    const float* m2 = (const float*)d_in[18];
    const float* v2 = (const float*)d_in[19];
    float* out = (float*)d_out;

    static const int mlp_smem = 12672 * 4;
    cudaFuncSetAttribute(mlp_kernel, cudaFuncAttributeMaxDynamicSharedMemorySize, mlp_smem);

    prep_kernel<<<1, 128>>>(w0, cb0, g0, b0, m0, v0,
                            w1, cb1, g1, b1, m1, v1,
                            w2, cb2, g2, b2, m2, v2);
    fps_p0_kernel<<<NB + (NB * NPT / 256), 256>>>(xyz, points, out);
    knn_kernel<<<dim3(NS, NB), 128>>>(xyz, out);
    mlp_kernel<<<(NB * NS) / 8, 256, mlp_smem>>>(xyz, out);
}

// round 2
// speedup vs baseline: 1.2923x; 1.2923x over previous
#include <cuda_runtime.h>

typedef unsigned long long u64;
typedef unsigned int u32;

#define NB 16
#define NPT 4096
#define NS 1024
#define NK 32

// ---------------- device scratch ----------------
__device__ __align__(16) float g_P0[NB * NPT * 64];
__device__ __align__(16) float g_W0x[3 * 64];
__device__ __align__(16) float g_W0p[64 * 64];
__device__ __align__(16) float g_B0[64];
__device__ __align__(16) float g_W1[64 * 64];
__device__ __align__(16) float g_B1[64];
__device__ __align__(16) float g_W2[64 * 128];
__device__ __align__(16) float g_B2[128];
__device__ int g_knn[NB * NS * NK];

// ---------------- packed f32x2 helpers ----------------
__device__ __forceinline__ u64 ffma2(u64 a, u64 b, u64 c) {
    u64 d; asm("fma.rn.f32x2 %0, %1, %2, %3;" : "=l"(d) : "l"(a), "l"(b), "l"(c)); return d;
}
__device__ __forceinline__ u64 add2(u64 a, u64 b) {
    u64 d; asm("add.rn.f32x2 %0, %1, %2;" : "=l"(d) : "l"(a), "l"(b)); return d;
}
__device__ __forceinline__ u64 mul2(u64 a, u64 b) {
    u64 d; asm("mul.rn.f32x2 %0, %1, %2;" : "=l"(d) : "l"(a), "l"(b)); return d;
}
__device__ __forceinline__ u64 dup2(float x) {
    u64 r; asm("mov.b64 %0, {%1, %1};" : "=l"(r) : "f"(x)); return r;
}
__device__ __forceinline__ u64 pack2f(float lo, float hi) {
    u64 r; asm("mov.b64 %0, {%1, %2};" : "=l"(r) : "f"(lo), "f"(hi)); return r;
}
__device__ __forceinline__ u64 packkey(u32 lo, u32 hi) {
    u64 r; asm("mov.b64 %0, {%1, %2};" : "=l"(r) : "r"(lo), "r"(hi)); return r;
}
__device__ __forceinline__ void unpack2(u64 a, float& lo, float& hi) {
    asm("mov.b64 {%0, %1}, %2;" : "=f"(lo), "=f"(hi) : "l"(a));
}

extern __shared__ float dynbuf[];

// ---------------- kernel 1: fold BN into weights ----------------
__global__ void prep_kernel(
    const float* w0, const float* cb0, const float* g0, const float* b0, const float* m0, const float* v0,
    const float* w1, const float* cb1, const float* g1, const float* b1, const float* m1, const float* v1,
    const float* w2, const float* cb2, const float* g2, const float* b2, const float* m2, const float* v2)
{
    int o = threadIdx.x;
    if (o < 64) {
        float s0 = g0[o] / sqrtf(v0[o] + 1e-5f);
        g_B0[o] = (cb0[o] - m0[o]) * s0 + b0[o];
        for (int i = 0; i < 3; i++)  g_W0x[i * 64 + o] = w0[o * 67 + i] * s0;
        for (int c = 0; c < 64; c++) g_W0p[c * 64 + o] = w0[o * 67 + 3 + c] * s0;
        float s1 = g1[o] / sqrtf(v1[o] + 1e-5f);
        g_B1[o] = (cb1[o] - m1[o]) * s1 + b1[o];
        for (int i = 0; i < 64; i++) g_W1[i * 64 + o] = w1[o * 64 + i] * s1;
    }
    if (o < 128) {
        float s2 = g2[o] / sqrtf(v2[o] + 1e-5f);
        g_B2[o] = (cb2[o] - m2[o]) * s2 + b2[o];
        for (int i = 0; i < 64; i++) g_W2[i * 128 + o] = w2[o * 64 + i] * s2;
    }
}

// ---------------- kernel 2: FPS (blocks 0..15) + P0 precompute ----------------
__global__ __launch_bounds__(256) void fps_p0_kernel(
    const float* __restrict__ xyz, const float* __restrict__ points, float* __restrict__ out_newxyz)
{
    if (blockIdx.x < NB) {
        float* sX = dynbuf;
        float* sY = dynbuf + NPT;
        float* sZ = dynbuf + 2 * NPT;
        u64* sKey = (u64*)(dynbuf + 3 * NPT);   // [2][8]

        int b = blockIdx.x, t = threadIdx.x;
        const float* xb = xyz + (size_t)b * NPT * 3;

        float fx[16], fy[16], fz[16], dd[16];
        u32 nlo[16];
#pragma unroll
        for (int j = 0; j < 16; j++) {
            int n = t + 256 * j;
            fx[j] = xb[n * 3 + 0]; fy[j] = xb[n * 3 + 1]; fz[j] = xb[n * 3 + 2];
            sX[n] = fx[j]; sY[n] = fy[j]; sZ[n] = fz[j];
            dd[j] = 1e10f;
            nlo[j] = ~(u32)n;
        }
        u64 PX[8], PY[8], PZ[8];
#pragma unroll
        for (int jp = 0; jp < 8; jp++) {
            PX[jp] = pack2f(fx[2 * jp], fx[2 * jp + 1]);
            PY[jp] = pack2f(fy[2 * jp], fy[2 * jp + 1]);
            PZ[jp] = pack2f(fz[2 * jp], fz[2 * jp + 1]);
        }
        __syncthreads();

        float cx = sX[0], cy = sY[0], cz = sZ[0];
        if (t == 0) {
            float* o0 = out_newxyz + (size_t)b * NS * 3;
            o0[0] = cx; o0[1] = cy; o0[2] = cz;
        }

        int lane = t & 31, w = t >> 5;
        for (int it = 0; it < NS - 1; it++) {
            u64 ncx = dup2(-cx), ncy = dup2(-cy), ncz = dup2(-cz);
            u64 best = 0;
#pragma unroll
            for (int jp = 0; jp < 8; jp++) {
                // (a + (-c)) is IEEE-identical to (a - c); all ops round-to-nearest,
                // reduction order (dx^2 + dy^2) + dz^2 matches reference exactly.
                u64 ax = add2(PX[jp], ncx); u64 sx = mul2(ax, ax);
                u64 ay = add2(PY[jp], ncy); u64 sy = mul2(ay, ay);
                u64 az = add2(PZ[jp], ncz); u64 sz = mul2(az, az);
                u64 s = add2(add2(sx, sy), sz);
                float da, db_; unpack2(s, da, db_);
                float n0 = fminf(dd[2 * jp], da);     dd[2 * jp] = n0;
                float n1 = fminf(dd[2 * jp + 1], db_); dd[2 * jp + 1] = n1;
                u64 k0 = packkey(nlo[2 * jp], __float_as_uint(n0));
                u64 k1 = packkey(nlo[2 * jp + 1], __float_as_uint(n1));
                u64 km = (k0 > k1) ? k0 : k1;
                best = (km > best) ? km : best;
            }
            u32 hi = (u32)(best >> 32);
            u32 H = __reduce_max_sync(0xffffffffu, hi);
            u32 cand = (hi == H) ? (u32)best : 0u;
            u32 L = __reduce_max_sync(0xffffffffu, cand);
            if (lane == 0) sKey[(it & 1) * 8 + w] = ((u64)H << 32) | (u64)L;
            __syncthreads();
            u64 g = sKey[(it & 1) * 8];
#pragma unroll
            for (int q = 1; q < 8; q++) { u64 k2 = sKey[(it & 1) * 8 + q]; g = (k2 > g) ? k2 : g; }
            int n = (int)((~(u32)g) & (NPT - 1));
            cx = sX[n]; cy = sY[n]; cz = sZ[n];
            if (t == 0) {
                float* oo = out_newxyz + ((size_t)b * NS + it + 1) * 3;
                oo[0] = cx; oo[1] = cy; oo[2] = cz;
            }
        }
    } else {
        // ---- P0: points @ (W0_pts * s0) + beta0 ----
        float* sW = dynbuf;  // 64*64 + 64 floats
        int pid = (blockIdx.x - NB) * 256 + threadIdx.x;
        for (int i = threadIdx.x; i < 64 * 64; i += 256) sW[i] = g_W0p[i];
        for (int i = threadIdx.x; i < 64; i += 256) sW[64 * 64 + i] = g_B0[i];
        __syncthreads();

        float xr[64];
        const float4* pr = (const float4*)(points + (size_t)pid * 64);
#pragma unroll
        for (int q = 0; q < 16; q++) {
            float4 v = __ldg(pr + q);
            xr[4 * q + 0] = v.x; xr[4 * q + 1] = v.y; xr[4 * q + 2] = v.z; xr[4 * q + 3] = v.w;
        }
        u64 acc[32];
        const u64* bb = (const u64*)(sW + 64 * 64);
#pragma unroll
        for (int q = 0; q < 32; q++) acc[q] = bb[q];
#pragma unroll
        for (int c = 0; c < 64; c++) {
            u64 xi = dup2(xr[c]);
            const ulonglong2* wr = (const ulonglong2*)(sW + c * 64);
#pragma unroll
            for (int q = 0; q < 16; q++) {
                ulonglong2 wv = wr[q];
                acc[2 * q]     = ffma2(xi, wv.x, acc[2 * q]);
                acc[2 * q + 1] = ffma2(xi, wv.y, acc[2 * q + 1]);
            }
        }
        ulonglong2* op = (ulonglong2*)(g_P0 + (size_t)pid * 64);
#pragma unroll
        for (int q = 0; q < 16; q++) op[q] = make_ulonglong2(acc[2 * q], acc[2 * q + 1]);
    }
}

// ---------------- kernel 3: KNN ----------------
__global__ __launch_bounds__(128) void knn_kernel(
    const float* __restrict__ xyz, const float* __restrict__ newxyz)
{
    int s = blockIdx.x, b = blockIdx.y;
    int t = threadIdx.x, lane = t & 31, w = t >> 5;
    const float* c3 = newxyz + ((size_t)b * NS + s) * 3;
    float cx = c3[0], cy = c3[1], cz = c3[2];
    const float* xb = xyz + (size_t)b * NPT * 3;

    float d[32];
#pragma unroll
    for (int j = 0; j < 32; j++) {
        int n = t + 128 * j;
        float dx = __ldg(xb + n * 3 + 0) - cx;
        float dy = __ldg(xb + n * 3 + 1) - cy;
        float dz = __ldg(xb + n * 3 + 2) - cz;
        d[j] = __fadd_rn(__fadd_rn(__fmul_rn(dx, dx), __fmul_rn(dy, dy)), __fmul_rn(dz, dz));
    }
    u64 lk = ~0ull;
#pragma unroll
    for (int j = 0; j < 32; j++) {
        u64 key = ((u64)__float_as_uint(d[j]) << 32) | (u32)(t + 128 * j);
        lk = (key < lk) ? key : lk;
    }
    __shared__ u64 sK[2][4];
    int* out = g_knn + ((size_t)b * NS + s) * NK;

    for (int r = 0; r < NK; r++) {
        u32 hi = (u32)(lk >> 32);
        u32 H = __reduce_min_sync(0xffffffffu, hi);
        u32 cand = (hi == H) ? (u32)lk : 0xffffffffu;
        u32 L = __reduce_min_sync(0xffffffffu, cand);
        if (lane == 0) sK[r & 1][w] = ((u64)H << 32) | (u64)L;
        __syncthreads();
        u64 g = sK[r & 1][0];
#pragma unroll
        for (int q = 1; q < 4; q++) { u64 k2 = sK[r & 1][q]; g = (k2 < g) ? k2 : g; }
        if (t == 0) out[r] = (int)((u32)g);
        if (lk == g) {
#pragma unroll
            for (int j = 0; j < 32; j++) {
                u64 key = ((u64)__float_as_uint(d[j]) << 32) | (u32)(t + 128 * j);
                if (key == g) d[j] = __uint_as_float(0x7f800000u);
            }
            lk = ~0ull;
#pragma unroll
            for (int j = 0; j < 32; j++) {
                u64 key = ((u64)__float_as_uint(d[j]) << 32) | (u32)(t + 128 * j);
                lk = (key < lk) ? key : lk;
            }
        }
    }
}

// ---------------- kernel 4: GEMM-tiled fused MLP + max over K ----------------
// Block handles 128 points (4 centroids x 32 neighbors). Register-tiled GEMM:
// layer1: thread tile 8M x 4N, layer2: 8M x 8N, m-pairs packed in f32x2.
__global__ __launch_bounds__(256, 1) void mlp_kernel(
    const float* __restrict__ xyz, float* __restrict__ out)
{
    float* sAct  = dynbuf;            // [64][132] = 8448
    float* sW1   = dynbuf + 8448;     // 4096
    float* sW2   = dynbuf + 12544;    // 8192
    float* sB1   = dynbuf + 20736;    // 64
    float* sB2   = dynbuf + 20800;    // 128
    float* sW0x  = dynbuf + 20928;    // 192
    float* sPmax = dynbuf + 21120;    // [16][128] = 2048

    int t = threadIdx.x;
    for (int i = t; i < 4096; i += 256) sW1[i] = g_W1[i];
    for (int i = t; i < 8192; i += 256) sW2[i] = g_W2[i];
    if (t < 64)  sB1[t] = g_B1[t];
    if (t < 128) sB2[t] = g_B2[t];
    if (t < 192) sW0x[t] = g_W0x[t];
    __syncthreads();

    // ---- layer 0: build act[k=64ch][m=128pts]  (2 threads per point) ----
    {
        int p = t & 127, h = t >> 7;
        int sg = blockIdx.x * 4 + (p >> 5);
        int b = sg >> 10;
        int n = g_knn[sg * NK + (p & 31)];
        const float* cc = out + (size_t)sg * 3;
        const float* xp = xyz + ((size_t)b * NPT + n) * 3;
        float gx = xp[0] - cc[0], gy = xp[1] - cc[1], gz = xp[2] - cc[2];
        u64 dgx = dup2(gx), dgy = dup2(gy), dgz = dup2(gz);
        const ulonglong2* pr  = (const ulonglong2*)(g_P0 + ((size_t)b * NPT + n) * 64 + h * 32);
        const ulonglong2* wxa = (const ulonglong2*)(sW0x + h * 32);
        const ulonglong2* wxb = (const ulonglong2*)(sW0x + 64 + h * 32);
        const ulonglong2* wxc = (const ulonglong2*)(sW0x + 128 + h * 32);
#pragma unroll
        for (int q = 0; q < 8; q++) {
            ulonglong2 pv = __ldg(pr + q);
            ulonglong2 wa = wxa[q], wb = wxb[q], wc = wxc[q];
            u64 a0 = ffma2(dgx, wa.x, pv.x); a0 = ffma2(dgy, wb.x, a0); a0 = ffma2(dgz, wc.x, a0);
            u64 a1 = ffma2(dgx, wa.y, pv.y); a1 = ffma2(dgy, wb.y, a1); a1 = ffma2(dgz, wc.y, a1);
            float v0, v1, v2, v3;
            unpack2(a0, v0, v1); unpack2(a1, v2, v3);
            int j0 = h * 32 + q * 4;
            sAct[(j0 + 0) * 132 + p] = fmaxf(v0, 0.f);
            sAct[(j0 + 1) * 132 + p] = fmaxf(v1, 0.f);
            sAct[(j0 + 2) * 132 + p] = fmaxf(v2, 0.f);
            sAct[(j0 + 3) * 132 + p] = fmaxf(v3, 0.f);
        }
    }
    __syncthreads();

    int mt = t >> 4, nt = t & 15;

    // ---- layer 1: [128,64] @ [64,64], thread tile 8M x 4N ----
    u64 acc[4][4];
#pragma unroll
    for (int nn = 0; nn < 4; nn++) {
        u64 bz = dup2(sB1[nt * 4 + nn]);
        acc[nn][0] = bz; acc[nn][1] = bz; acc[nn][2] = bz; acc[nn][3] = bz;
    }
    {
        const ulonglong2* A  = (const ulonglong2*)(sAct + mt * 8);   // stride 33 u128/row
        const float4* Bw = (const float4*)(sW1 + nt * 4);            // stride 16 f4/row
#pragma unroll
        for (int k = 0; k < 64; k++) {
            ulonglong2 a01 = A[k * 33], a23 = A[k * 33 + 1];
            float4 bw = Bw[k * 16];
            u64 b0 = dup2(bw.x), b1 = dup2(bw.y), b2 = dup2(bw.z), b3 = dup2(bw.w);
            acc[0][0] = ffma2(b0, a01.x, acc[0][0]); acc[0][1] = ffma2(b0, a01.y, acc[0][1]);
            acc[0][2] = ffma2(b0, a23.x, acc[0][2]); acc[0][3] = ffma2(b0, a23.y, acc[0][3]);
            acc[1][0] = ffma2(b1, a01.x, acc[1][0]); acc[1][1] = ffma2(b1, a01.y, acc[1][1]);
            acc[1][2] = ffma2(b1, a23.x, acc[1][2]); acc[1][3] = ffma2(b1, a23.y, acc[1][3]);
            acc[2][0] = ffma2(b2, a01.x, acc[2][0]); acc[2][1] = ffma2(b2, a01.y, acc[2][1]);
            acc[2][2] = ffma2(b2, a23.x, acc[2][2]); acc[2][3] = ffma2(b2, a23.y, acc[2][3]);
            acc[3][0] = ffma2(b3, a01.x, acc[3][0]); acc[3][1] = ffma2(b3, a01.y, acc[3][1]);
            acc[3][2] = ffma2(b3, a23.x, acc[3][2]); acc[3][3] = ffma2(b3, a23.y, acc[3][3]);
        }
    }
    __syncthreads();   // all layer-1 reads of sAct complete
    // relu + write act2[k=n][m] back into sAct
#pragma unroll
    for (int nn = 0; nn < 4; nn++) {
        int row = nt * 4 + nn;
#pragma unroll
        for (int mp = 0; mp < 4; mp++) {
            float lo, hi; unpack2(acc[nn][mp], lo, hi);
            *(u64*)(sAct + row * 132 + mt * 8 + mp * 2) = pack2f(fmaxf(lo, 0.f), fmaxf(hi, 0.f));
        }
    }
    __syncthreads();

    // ---- layer 2: [128,64] @ [64,128], thread tile 8M x 8N ----
    u64 acc2[8][4];
#pragma unroll
    for (int nn = 0; nn < 8; nn++) {
        u64 bz = dup2(sB2[nt * 8 + nn]);
        acc2[nn][0] = bz; acc2[nn][1] = bz; acc2[nn][2] = bz; acc2[nn][3] = bz;
    }
    {
        const ulonglong2* A = (const ulonglong2*)(sAct + mt * 8);
        const float4* Bw = (const float4*)(sW2 + nt * 8);            // stride 32 f4/row
#pragma unroll
        for (int k = 0; k < 64; k++) {
            ulonglong2 a01 = A[k * 33], a23 = A[k * 33 + 1];
            float4 w04 = Bw[k * 32], w48 = Bw[k * 32 + 1];
            u64 b0 = dup2(w04.x), b1 = dup2(w04.y), b2 = dup2(w04.z), b3 = dup2(w04.w);
            u64 b4 = dup2(w48.x), b5 = dup2(w48.y), b6 = dup2(w48.z), b7 = dup2(w48.w);
            acc2[0][0] = ffma2(b0, a01.x, acc2[0][0]); acc2[0][1] = ffma2(b0, a01.y, acc2[0][1]);
            acc2[0][2] = ffma2(b0, a23.x, acc2[0][2]); acc2[0][3] = ffma2(b0, a23.y, acc2[0][3]);
            acc2[1][0] = ffma2(b1, a01.x, acc2[1][0]); acc2[1][1] = ffma2(b1, a01.y, acc2[1][1]);
            acc2[1][2] = ffma2(b1, a23.x, acc2[1][2]); acc2[1][3] = ffma2(b1, a23.y, acc2[1][3]);
            acc2[2][0] = ffma2(b2, a01.x, acc2[2][0]); acc2[2][1] = ffma2(b2, a01.y, acc2[2][1]);
            acc2[2][2] = ffma2(b2, a23.x, acc2[2][2]); acc2[2][3] = ffma2(b2, a23.y, acc2[2][3]);
            acc2[3][0] = ffma2(b3, a01.x, acc2[3][0]); acc2[3][1] = ffma2(b3, a01.y, acc2[3][1]);
            acc2[3][2] = ffma2(b3, a23.x, acc2[3][2]); acc2[3][3] = ffma2(b3, a23.y, acc2[3][3]);
            acc2[4][0] = ffma2(b4, a01.x, acc2[4][0]); acc2[4][1] = ffma2(b4, a01.y, acc2[4][1]);
            acc2[4][2] = ffma2(b4, a23.x, acc2[4][2]); acc2[4][3] = ffma2(b4, a23.y, acc2[4][3]);
            acc2[5][0] = ffma2(b5, a01.x, acc2[5][0]); acc2[5][1] = ffma2(b5, a01.y, acc2[5][1]);
            acc2[5][2] = ffma2(b5, a23.x, acc2[5][2]); acc2[5][3] = ffma2(b5, a23.y, acc2[5][3]);
            acc2[6][0] = ffma2(b6, a01.x, acc2[6][0]); acc2[6][1] = ffma2(b6, a01.y, acc2[6][1]);
            acc2[6][2] = ffma2(b6, a23.x, acc2[6][2]); acc2[6][3] = ffma2(b6, a23.y, acc2[6][3]);
            acc2[7][0] = ffma2(b7, a01.x, acc2[7][0]); acc2[7][1] = ffma2(b7, a01.y, acc2[7][1]);
            acc2[7][2] = ffma2(b7, a23.x, acc2[7][2]); acc2[7][3] = ffma2(b7, a23.y, acc2[7][3]);
        }
    }
    // relu + partial max over this thread's 8 m-rows (relu(max) == max(relu) since clamp at 0)
#pragma unroll
    for (int nn = 0; nn < 8; nn++) {
        float mm = -1e30f;
#pragma unroll
        for (int mp = 0; mp < 4; mp++) {
            float lo, hi; unpack2(acc2[nn][mp], lo, hi);
            mm = fmaxf(mm, fmaxf(lo, hi));
        }
        sPmax[mt * 128 + nt * 8 + nn] = fmaxf(mm, 0.f);
    }
    __syncthreads();
    // final max across 4 m-tiles per centroid; write [b][ch][s] as float4 over 4 centroids
    if (t < 128) {
        int ch = t;
        int sg0 = blockIdx.x * 4;
        int b = sg0 >> 10, s0 = sg0 & (NS - 1);
        float4 v;
        v.x = fmaxf(fmaxf(sPmax[ 0 * 128 + ch], sPmax[ 1 * 128 + ch]),
                    fmaxf(sPmax[ 2 * 128 + ch], sPmax[ 3 * 128 + ch]));
        v.y = fmaxf(fmaxf(sPmax[ 4 * 128 + ch], sPmax[ 5 * 128 + ch]),
                    fmaxf(sPmax[ 6 * 128 + ch], sPmax[ 7 * 128 + ch]));
        v.z = fmaxf(fmaxf(sPmax[ 8 * 128 + ch], sPmax[ 9 * 128 + ch]),
                    fmaxf(sPmax[10 * 128 + ch], sPmax[11 * 128 + ch]));
        v.w = fmaxf(fmaxf(sPmax[12 * 128 + ch], sPmax[13 * 128 + ch]),
                    fmaxf(sPmax[14 * 128 + ch], sPmax[15 * 128 + ch]));
        *(float4*)(out + (size_t)NB * NS * 3 + ((size_t)(b * 128 + ch)) * NS + s0) = v;
    }
}

// ---------------- launch ----------------
extern "C" void kernel_launch(void* const* d_in, const int* in_sizes, int n_in,
                              void* d_out, int out_size)
{
    const float* xyz = (const float*)d_in[0];
    const float* points = (const float*)d_in[1];
    const float* w0 = (const float*)d_in[2];
    const float* cb0 = (const float*)d_in[3];
    const float* g0 = (const float*)d_in[4];
    const float* b0 = (const float*)d_in[5];
    const float* m0 = (const float*)d_in[6];
    const float* v0 = (const float*)d_in[7];
    const float* w1 = (const float*)d_in[8];
    const float* cb1 = (const float*)d_in[9];
    const float* g1 = (const float*)d_in[10];
    const float* b1 = (const float*)d_in[11];
    const float* m1 = (const float*)d_in[12];
    const float* v1 = (const float*)d_in[13];
    const float* w2 = (const float*)d_in[14];
    const float* cb2 = (const float*)d_in[15];
    const float* g2 = (const float*)d_in[16];
    const float* b2 = (const float*)d_in[17];
    const float* m2 = (const float*)d_in[18];
    const float* v2 = (const float*)d_in[19];
    float* out = (float*)d_out;

    const int fps_smem = (3 * NPT) * 4 + 128;       // 49280 B
    const int mlp_smem = 23168 * 4;                 // 92672 B
    cudaFuncSetAttribute(fps_p0_kernel, cudaFuncAttributeMaxDynamicSharedMemorySize, fps_smem);
    cudaFuncSetAttribute(mlp_kernel, cudaFuncAttributeMaxDynamicSharedMemorySize, mlp_smem);

    prep_kernel<<<1, 128>>>(w0, cb0, g0, b0, m0, v0,
                            w1, cb1, g1, b1, m1, v1,
                            w2, cb2, g2, b2, m2, v2);
    fps_p0_kernel<<<NB + (NB * NPT / 256), 256, fps_smem>>>(xyz, points, out);
    knn_kernel<<<dim3(NS, NB), 128>>>(xyz, out);
    mlp_kernel<<<(NB * NS) / 4, 256, mlp_smem>>>(xyz, out);
}